// round 15
// baseline (speedup 1.0000x reference)
#include <cuda_runtime.h>
#include <math.h>

#define B   32
#define L   64
#define DQ  1024
#define C   512
#define NH  8
#define DK  64
#define HW  1024
#define TEMP_INV 0.125f   // 1/sqrt(64)

typedef unsigned long long ull;

__device__ __forceinline__ ull pack2(float lo, float hi) {
    ull r; asm("mov.b64 %0, {%1,%2};" : "=l"(r) : "f"(lo), "f"(hi)); return r;
}
__device__ __forceinline__ void ffma2(ull& d, ull a, ull b) {
    asm("fma.rn.f32x2 %0, %1, %2, %0;" : "+l"(d) : "l"(a), "l"(b));
}
__device__ __forceinline__ float2 unpack2(ull v) {
    float2 f; asm("mov.b64 {%0,%1}, %2;" : "=f"(f.x), "=f"(f.y) : "l"(v)); return f;
}
__device__ __forceinline__ void red_v4(float* dst, float a, float b, float c, float d) {
    asm volatile("red.global.add.v4.f32 [%0], {%1,%2,%3,%4};"
                 :: "l"(dst), "f"(a), "f"(b), "f"(c), "f"(d) : "memory");
}

// ---------------- scratch (zero-initialized at module load) ----------------
__device__ __align__(16) float g_qs  [B*DQ];
__device__ __align__(16) float g_qsum[B*C];
__device__ __align__(16) float g_wqc [B*C*NH];      // [b][c][n]
__device__ __align__(16) float g_wqd [B*C*NH];      // [b][c][n]
__device__              float g_bqc [B*NH];
__device__              float g_bqd [B*NH];
__device__ __align__(16) float g_score[B*HW*16];    // [b][s][16] — ALWAYS left zeroed
__device__ __align__(16) ull   g_p   [B*HW*4];      // [b][s*4+np] packed (p_2np, p_2np+1)
__device__ __align__(16) float g_dif [B*NH*HW];     // [b][n][s]
__device__ __align__(16) float g_vbar[B*NH*C];
__device__ __align__(16) float g_attn[B*C];
__device__ unsigned int g_cnt[B];                   // last-block tickets — always left zeroed

// ---- K1: qs[b,dq] = sum_l q[b,l,dq] ----
__global__ void k_qsum_l(const float* __restrict__ q) {
    int b = blockIdx.x;
    int d = blockIdx.y * 512 + threadIdx.x;
    const float* p = q + (size_t)b * L * DQ + d;
    float s = 0.f;
#pragma unroll
    for (int l = 0; l < L; l++) s += p[(size_t)l * DQ];
    g_qs[b * DQ + d] = s;
}

// ---- K2: q_sum[b,o] = qs[b,:].w[o,:] + L*bias[o]. grid (16 oc, 8 bc of 4), block 128 ----
__global__ void __launch_bounds__(128) k_qproj(const float* __restrict__ w,
                                               const float* __restrict__ bias) {
    __shared__ __align__(16) float sq[4 * (DQ + 4)];
    int oc = blockIdx.x, bstart = blockIdx.y * 4;
    int tid = threadIdx.x;
    for (int i = tid; i < 4 * DQ / 4; i += 128) {
        int bb = i >> 8, c4 = i & 255;
        *(float4*)(sq + bb * (DQ + 4) + c4 * 4) =
            ((const float4*)g_qs)[(size_t)(bstart + bb) * 256 + c4];
    }
    __syncthreads();
    int o_local = tid >> 2, bb = tid & 3;
    int o = oc * 32 + o_local;
    const float4* wr = (const float4*)(w + (size_t)o * DQ);
    const float4* qr = (const float4*)(sq + bb * (DQ + 4));
    float acc = (float)L * bias[o];
#pragma unroll 8
    for (int k = 0; k < DQ / 4; k++) {
        float4 a = wr[k], x = qr[k];
        acc += a.x * x.x + a.y * x.y + a.z * x.z + a.w * x.w;
    }
    g_qsum[(bstart + bb) * C + o] = acc;
}

// ---- K3: wq[b][c][n] + bias dots. grid (NH, 8 bc of 4), block 512 ----
__global__ void __launch_bounds__(512) k_wq(const float* __restrict__ wkc, const float* __restrict__ bkc,
                                            const float* __restrict__ wkd, const float* __restrict__ bkd) {
    __shared__ float sq[4][DK];
    int n = blockIdx.x, bstart = blockIdx.y * 4;
    int c = threadIdx.x;
    if (c < 4 * DK) {
        int bb = c >> 6, d = c & 63;
        sq[bb][d] = g_qsum[(bstart + bb) * C + n * DK + d];
    }
    __syncthreads();
    float ac[4], ad[4];
#pragma unroll
    for (int bb = 0; bb < 4; bb++) { ac[bb] = 0.f; ad[bb] = 0.f; }
#pragma unroll 4
    for (int d = 0; d < DK; d++) {
        float wc = wkc[(size_t)(n * DK + d) * C + c];
        float wd = wkd[(size_t)(n * DK + d) * C + c];
#pragma unroll
        for (int bb = 0; bb < 4; bb++) {
            ac[bb] += wc * sq[bb][d];
            ad[bb] += wd * sq[bb][d];
        }
    }
#pragma unroll
    for (int bb = 0; bb < 4; bb++) {
        size_t idx = ((size_t)(bstart + bb) * C + c) * NH + n;
        g_wqc[idx] = ac[bb];
        g_wqd[idx] = ad[bb];
    }
    if (c < 4) {
        float s1 = 0.f, s2 = 0.f;
        for (int d = 0; d < DK; d++) {
            s1 += bkc[n * DK + d] * sq[c][d];
            s2 += bkd[n * DK + d] * sq[c][d];
        }
        int bn = (bstart + c) * NH + n;
        g_bqc[bn] = s1; g_bqd[bn] = s2;
    }
}

// ---- K4: score partials + fused finalize. grid (B, 4 sh, 8 cc), block 128, 2 s/thread ----
// Last block per b (ticket) runs the softmax/sigmoid finalize tail and re-zeroes g_score.
__global__ void __launch_bounds__(128) k_scores_part(const float* __restrict__ v) {
    __shared__ __align__(16) float sw[64 * 16];   // [c][16]: 0-7 wqc, 8-15 wqd. 4KB
    __shared__ unsigned int s_last;
    __shared__ float redm[4][8], redz[4][8], Mfin[8], Zfin[8];
    int b = blockIdx.x, sh = blockIdx.y, cc = blockIdx.z;
    int tid = threadIdx.x;
    int cbase = cc * 64;
    for (int i = tid; i < 256; i += 128) {
        int ci = i >> 2, part = i & 3;
        const float* src = ((part < 2) ? g_wqc : g_wqd)
                         + ((size_t)(b * C + cbase + ci)) * NH + (part & 1) * 4;
        *(float4*)(sw + ci * 16 + ((part < 2) ? 0 : 8) + (part & 1) * 4) = *(const float4*)src;
    }
    __syncthreads();
    int s0 = sh * 256 + tid * 2;
    const float* vbase = v + ((size_t)(b * C + cbase)) * HW + s0;
    ull acc[2][8];
#pragma unroll
    for (int si = 0; si < 2; si++)
#pragma unroll
        for (int kp = 0; kp < 8; kp++) acc[si][kp] = 0ull;
    float2 cur[4], nxt[4];
#pragma unroll
    for (int u = 0; u < 4; u++) cur[u] = *(const float2*)(vbase + (size_t)u * HW);
#pragma unroll 2
    for (int cb = 0; cb < 64; cb += 4) {
        if (cb + 4 < 64) {
#pragma unroll
            for (int u = 0; u < 4; u++)
                nxt[u] = *(const float2*)(vbase + (size_t)(cb + 4 + u) * HW);
        }
#pragma unroll
        for (int u = 0; u < 4; u++) {
            const ulonglong2* w2 = (const ulonglong2*)(sw + (cb + u) * 16);
            ulonglong2 wa = w2[0], wb = w2[1], wc = w2[2], wd = w2[3];
            float2 cv = cur[u];
            ull v0 = pack2(cv.x, cv.x);
            ull v1 = pack2(cv.y, cv.y);
            ffma2(acc[0][0], v0, wa.x); ffma2(acc[0][1], v0, wa.y);
            ffma2(acc[0][2], v0, wb.x); ffma2(acc[0][3], v0, wb.y);
            ffma2(acc[0][4], v0, wc.x); ffma2(acc[0][5], v0, wc.y);
            ffma2(acc[0][6], v0, wd.x); ffma2(acc[0][7], v0, wd.y);
            ffma2(acc[1][0], v1, wa.x); ffma2(acc[1][1], v1, wa.y);
            ffma2(acc[1][2], v1, wb.x); ffma2(acc[1][3], v1, wb.y);
            ffma2(acc[1][4], v1, wc.x); ffma2(acc[1][5], v1, wc.y);
            ffma2(acc[1][6], v1, wd.x); ffma2(acc[1][7], v1, wd.y);
        }
#pragma unroll
        for (int u = 0; u < 4; u++) cur[u] = nxt[u];
    }
#pragma unroll
    for (int si = 0; si < 2; si++) {
        float* dst = g_score + ((size_t)b * HW + s0 + si) * 16;
        float2 f0 = unpack2(acc[si][0]), f1 = unpack2(acc[si][1]);
        float2 f2 = unpack2(acc[si][2]), f3 = unpack2(acc[si][3]);
        float2 f4 = unpack2(acc[si][4]), f5 = unpack2(acc[si][5]);
        float2 f6 = unpack2(acc[si][6]), f7 = unpack2(acc[si][7]);
        red_v4(dst,      f0.x, f0.y, f1.x, f1.y);
        red_v4(dst + 4,  f2.x, f2.y, f3.x, f3.y);
        red_v4(dst + 8,  f4.x, f4.y, f5.x, f5.y);
        red_v4(dst + 12, f6.x, f6.y, f7.x, f7.y);
    }
    // ---- last-block ticket ----
    __threadfence();
    if (tid == 0) s_last = (atomicAdd(&g_cnt[b], 1u) == 31u) ? 1u : 0u;
    __syncthreads();
    if (!s_last) return;
    if (tid == 0) g_cnt[b] = 0;               // reset for next replay
    int lane = tid & 31, warp = tid >> 5;
    int bn0 = b * NH;
    // Pass A: per-head max over raw c-scores (monotonic under bias+scale)
    float mloc[8];
#pragma unroll
    for (int n = 0; n < NH; n++) mloc[n] = -1e30f;
#pragma unroll 2
    for (int k = 0; k < 8; k++) {
        const float4* gs = (const float4*)(g_score + ((size_t)b * HW + tid + k * 128) * 16);
        float4 r0 = gs[0], r1 = gs[1];
        mloc[0] = fmaxf(mloc[0], r0.x); mloc[1] = fmaxf(mloc[1], r0.y);
        mloc[2] = fmaxf(mloc[2], r0.z); mloc[3] = fmaxf(mloc[3], r0.w);
        mloc[4] = fmaxf(mloc[4], r1.x); mloc[5] = fmaxf(mloc[5], r1.y);
        mloc[6] = fmaxf(mloc[6], r1.z); mloc[7] = fmaxf(mloc[7], r1.w);
    }
#pragma unroll
    for (int n = 0; n < NH; n++) {
        float mm = mloc[n];
#pragma unroll
        for (int o = 16; o; o >>= 1) mm = fmaxf(mm, __shfl_xor_sync(0xffffffffu, mm, o));
        if (lane == 0) redm[warp][n] = mm;
    }
    __syncthreads();
    if (tid < 8) {
        float mm = fmaxf(fmaxf(redm[0][tid], redm[1][tid]), fmaxf(redm[2][tid], redm[3][tid]));
        Mfin[tid] = mm;
    }
    __syncthreads();
    // Pass B: Z = sum exp((raw - M)*t)
    float zloc[8];
#pragma unroll
    for (int n = 0; n < NH; n++) zloc[n] = 0.f;
#pragma unroll 2
    for (int k = 0; k < 8; k++) {
        const float4* gs = (const float4*)(g_score + ((size_t)b * HW + tid + k * 128) * 16);
        float4 r0 = gs[0], r1 = gs[1];
        zloc[0] += expf((r0.x - Mfin[0]) * TEMP_INV);
        zloc[1] += expf((r0.y - Mfin[1]) * TEMP_INV);
        zloc[2] += expf((r0.z - Mfin[2]) * TEMP_INV);
        zloc[3] += expf((r0.w - Mfin[3]) * TEMP_INV);
        zloc[4] += expf((r1.x - Mfin[4]) * TEMP_INV);
        zloc[5] += expf((r1.y - Mfin[5]) * TEMP_INV);
        zloc[6] += expf((r1.z - Mfin[6]) * TEMP_INV);
        zloc[7] += expf((r1.w - Mfin[7]) * TEMP_INV);
    }
#pragma unroll
    for (int n = 0; n < NH; n++) {
        float z = zloc[n];
#pragma unroll
        for (int o = 16; o; o >>= 1) z += __shfl_xor_sync(0xffffffffu, z, o);
        if (lane == 0) redz[warp][n] = z;
    }
    __syncthreads();
    if (tid < 8)
        Zfin[tid] = 1.f / (redz[0][tid] + redz[1][tid] + redz[2][tid] + redz[3][tid]);
    __syncthreads();
    // Pass C: write packed p, sigmoid dif, zero g_score
#pragma unroll 1
    for (int k = 0; k < 8; k++) {
        int s = tid + k * 128;
        float4* gs = (float4*)(g_score + ((size_t)b * HW + s) * 16);
        float4 r0 = gs[0], r1 = gs[1], r2 = gs[2], r3 = gs[3];
        float e0 = expf((r0.x - Mfin[0]) * TEMP_INV) * Zfin[0];
        float e1 = expf((r0.y - Mfin[1]) * TEMP_INV) * Zfin[1];
        float e2 = expf((r0.z - Mfin[2]) * TEMP_INV) * Zfin[2];
        float e3 = expf((r0.w - Mfin[3]) * TEMP_INV) * Zfin[3];
        float e4 = expf((r1.x - Mfin[4]) * TEMP_INV) * Zfin[4];
        float e5 = expf((r1.y - Mfin[5]) * TEMP_INV) * Zfin[5];
        float e6 = expf((r1.z - Mfin[6]) * TEMP_INV) * Zfin[6];
        float e7 = expf((r1.w - Mfin[7]) * TEMP_INV) * Zfin[7];
        ull* gp = g_p + ((size_t)b * HW + s) * 4;
        ulonglong2 p01, p23;
        p01.x = pack2(e0, e1); p01.y = pack2(e2, e3);
        p23.x = pack2(e4, e5); p23.y = pack2(e6, e7);
        *(ulonglong2*)gp = p01;
        *(ulonglong2*)(gp + 2) = p23;
        float y0 = (r2.x + g_bqd[bn0 + 0]) * TEMP_INV;
        float y1 = (r2.y + g_bqd[bn0 + 1]) * TEMP_INV;
        float y2 = (r2.z + g_bqd[bn0 + 2]) * TEMP_INV;
        float y3 = (r2.w + g_bqd[bn0 + 3]) * TEMP_INV;
        float y4 = (r3.x + g_bqd[bn0 + 4]) * TEMP_INV;
        float y5 = (r3.y + g_bqd[bn0 + 5]) * TEMP_INV;
        float y6 = (r3.z + g_bqd[bn0 + 6]) * TEMP_INV;
        float y7 = (r3.w + g_bqd[bn0 + 7]) * TEMP_INV;
        g_dif[(size_t)(bn0 + 0) * HW + s] = 1.f / (1.f + expf(-y0));
        g_dif[(size_t)(bn0 + 1) * HW + s] = 1.f / (1.f + expf(-y1));
        g_dif[(size_t)(bn0 + 2) * HW + s] = 1.f / (1.f + expf(-y2));
        g_dif[(size_t)(bn0 + 3) * HW + s] = 1.f / (1.f + expf(-y3));
        g_dif[(size_t)(bn0 + 4) * HW + s] = 1.f / (1.f + expf(-y4));
        g_dif[(size_t)(bn0 + 5) * HW + s] = 1.f / (1.f + expf(-y5));
        g_dif[(size_t)(bn0 + 6) * HW + s] = 1.f / (1.f + expf(-y6));
        g_dif[(size_t)(bn0 + 7) * HW + s] = 1.f / (1.f + expf(-y7));
        float4 z4 = make_float4(0.f, 0.f, 0.f, 0.f);
        gs[0] = z4; gs[1] = z4; gs[2] = z4; gs[3] = z4;
    }
    // NOTE: correctness: the c-branch bias g_bqc cancels in softmax
    // ((raw+bq-M')*t with M'=(Mraw+bq) equals (raw-Mraw)*t), so it is
    // intentionally never applied here.
}

// ---- K5: vbar[b,n,c] = sum_s p[s,n] v[b,c,s]. grid (B,16 cc of 32), block 256 ----
__global__ void __launch_bounds__(256) k_vbar(const float* __restrict__ v) {
    __shared__ __align__(16) ull sp[4352];          // swizzled: phys = i + (i>>4), i = s*4+np
    int b = blockIdx.x, t = threadIdx.x;
    {
        const ull* gp = g_p + (size_t)b * HW * 4;
        for (int i = t; i < 4096; i += 256) sp[i + (i >> 4)] = gp[i];
    }
    __syncthreads();
    int warp = t >> 5, lane = t & 31;
    int c0 = blockIdx.y * 32 + warp * 4;
    const float* vb = v + (size_t)(b * C + c0) * HW;
    ull acc[4][4];
#pragma unroll
    for (int ci = 0; ci < 4; ci++)
#pragma unroll
        for (int np = 0; np < 4; np++) acc[ci][np] = 0ull;
    float4 vv[4], vn[4];
#pragma unroll
    for (int ci = 0; ci < 4; ci++)
        vv[ci] = *(const float4*)(vb + (size_t)ci * HW + lane * 4);
#pragma unroll 1
    for (int it = 0; it < 8; it++) {
        if (it < 7) {
#pragma unroll
            for (int ci = 0; ci < 4; ci++)
                vn[ci] = *(const float4*)(vb + (size_t)ci * HW + (it + 1) * 128 + lane * 4);
        }
        int sb = it * 32 + lane;
#pragma unroll
        for (int si = 0; si < 4; si++) {
            int s = it * 128 + lane * 4 + si;
            int phys = 4 * s + sb;
            ull pA0 = sp[phys];
            ull pA1 = sp[phys + 1];
            ull pB0 = sp[phys + 2];
            ull pB1 = sp[phys + 3];
#pragma unroll
            for (int ci = 0; ci < 4; ci++) {
                float vs = ((const float*)&vv[ci])[si];
                ull vd = pack2(vs, vs);
                ffma2(acc[ci][0], vd, pA0);
                ffma2(acc[ci][1], vd, pA1);
                ffma2(acc[ci][2], vd, pB0);
                ffma2(acc[ci][3], vd, pB1);
            }
        }
#pragma unroll
        for (int ci = 0; ci < 4; ci++) vv[ci] = vn[ci];
    }
#pragma unroll
    for (int ci = 0; ci < 4; ci++) {
#pragma unroll
        for (int np = 0; np < 4; np++) {
            float2 f = unpack2(acc[ci][np]);
#pragma unroll
            for (int o = 16; o; o >>= 1) {
                f.x += __shfl_xor_sync(0xffffffffu, f.x, o);
                f.y += __shfl_xor_sync(0xffffffffu, f.y, o);
            }
            if (lane == 0) {
                g_vbar[(size_t)(b * NH + 2 * np) * C + c0 + ci]     = f.x;
                g_vbar[(size_t)(b * NH + 2 * np + 1) * C + c0 + ci] = f.y;
            }
        }
    }
}

// ---- K6: attn[b,o] = w_vs[o,:].vbar[b,head(o),:]+bias. grid (NH, 8 bc of 4), block 256 ----
__global__ void __launch_bounds__(256) k_attn(const float* __restrict__ wvs,
                                              const float* __restrict__ bvs) {
    __shared__ __align__(16) float svb[4 * (C + 4)];
    int n = blockIdx.x, bstart = blockIdx.y * 4;
    int tid = threadIdx.x;
    for (int i = tid; i < 4 * C / 4; i += 256) {
        int bb = i >> 7, c4 = i & 127;
        *(float4*)(svb + bb * (C + 4) + c4 * 4) =
            ((const float4*)g_vbar)[(size_t)((bstart + bb) * NH + n) * 128 + c4];
    }
    __syncthreads();
    int o_local = tid >> 2, bb = tid & 3;
    int o = n * DK + o_local;
    const float4* wr = (const float4*)(wvs + (size_t)o * C);
    const float4* xr = (const float4*)(svb + bb * (C + 4));
    float acc = bvs[o];
#pragma unroll 8
    for (int k = 0; k < C / 4; k++) {
        float4 a = wr[k], x = xr[k];
        acc += a.x * x.x + a.y * x.y + a.z * x.z + a.w * x.w;
    }
    g_attn[(bstart + bb) * C + o] = acc;
}

// ---- K7: out + attn_map (streamer), 4 c per CTA ----
__global__ void __launch_bounds__(256) k_out(const float* __restrict__ v, const float* __restrict__ gam,
                      const float* __restrict__ bet, const float* __restrict__ mean,
                      const float* __restrict__ var, float* __restrict__ out,
                      float* __restrict__ amap) {
    __shared__ float sd[HW + HW / 32];
    int blk = blockIdx.x;                 // b*128 + cchunk
    int b = blk >> 7, cbase = (blk & 127) * 4, n = cbase >> 6;
    int t4 = threadIdx.x * 4;
    const float* gdif = g_dif + (size_t)(b * NH + n) * HW;
#pragma unroll
    for (int u = 0; u < 4; u++) { int s = t4 + u; sd[s + (s >> 5)] = gdif[s]; }
    __syncthreads();
    int i0 = t4 >> 5, j0 = t4 & 31;
    float dd[4];
#pragma unroll
    for (int u = 0; u < 4; u++) dd[u] = sd[(j0 + u) * 33 + i0];
#pragma unroll
    for (int u = 0; u < 4; u++) {
        int c = cbase + u;
        float a  = g_attn[b * C + c];
        float sc = gam[c] * rsqrtf(var[c] + 1e-5f);
        float mn = mean[c], bt = bet[c];
        size_t base = ((size_t)(b * C + c)) * HW + t4;
        float4 rv = *(const float4*)(v + base);
        const float* rvp = (const float*)&rv;
        float vals[4], os[4];
#pragma unroll
        for (int k = 0; k < 4; k++) {
            float val = dd[k] * a;
            vals[k] = val;
            float o2 = (val - mn) * sc + bt + rvp[k];
            os[k] = o2 >= 0.f ? o2 : 0.1f * o2;
        }
        *(float4*)(amap + base) = *(float4*)vals;
        *(float4*)(out  + base) = *(float4*)os;
    }
}

// ---- K8: m_attn; sA parallelized over 576 threads ----
__global__ void k_m(const float* __restrict__ wm, const float* __restrict__ wmb,
                    float* __restrict__ m) {
    __shared__ float sd[NH][HW + 32];
    __shared__ float sA[NH * 9];
    int b = blockIdx.x, t = threadIdx.x;
    for (int n = 0; n < NH; n++) { int s = t; sd[n][s + (s >> 5)] = g_dif[(size_t)(b * NH + n) * HW + s]; }
    if (t < 576) {
        int g = t >> 3, sub = t & 7;       // g in [0,72), groups of 8 within a warp
        int nn = g / 9, k = g - nn * 9;
        float a = 0.f;
#pragma unroll
        for (int dd = 0; dd < 8; dd++) {
            int d = sub + dd * 8;
            a += g_attn[b * C + nn * DK + d] * wm[(size_t)(nn * DK + d) * 9 + k];
        }
        a += __shfl_xor_sync(0xffffffffu, a, 4);
        a += __shfl_xor_sync(0xffffffffu, a, 2);
        a += __shfl_xor_sync(0xffffffffu, a, 1);
        if (sub == 0) sA[g] = a;
    }
    __syncthreads();
    int i = t >> 5, j = t & 31;
    float acc = wmb[0];
#pragma unroll
    for (int n = 0; n < NH; n++) {
#pragma unroll
        for (int ki = 0; ki < 3; ki++) {
            int ii = i + ki - 1;
            if (ii < 0 || ii >= 32) continue;
#pragma unroll
            for (int kj = 0; kj < 3; kj++) {
                int jj = j + kj - 1;
                if (jj < 0 || jj >= 32) continue;
                acc += sA[n * 9 + ki * 3 + kj] * sd[n][jj * 33 + ii];
            }
        }
    }
    m[b * HW + i * 32 + j] = acc;
}

extern "C" void kernel_launch(void* const* d_in, const int* in_sizes, int n_in,
                              void* d_out, int out_size) {
    (void)in_sizes; (void)n_in; (void)out_size;
    const float* q      = (const float*)d_in[0];
    const float* v      = (const float*)d_in[1];
    const float* w_qs_w = (const float*)d_in[3];
    const float* w_qs_b = (const float*)d_in[4];
    const float* w_kc_w = (const float*)d_in[7];
    const float* w_kc_b = (const float*)d_in[8];
    const float* w_kd_w = (const float*)d_in[9];
    const float* w_kd_b = (const float*)d_in[10];
    const float* w_vs_w = (const float*)d_in[11];
    const float* w_vs_b = (const float*)d_in[12];
    const float* w_m_w  = (const float*)d_in[13];
    const float* w_m_b  = (const float*)d_in[14];
    const float* bn_g   = (const float*)d_in[15];
    const float* bn_b   = (const float*)d_in[16];
    const float* bn_m   = (const float*)d_in[17];
    const float* bn_v   = (const float*)d_in[18];

    float* out    = (float*)d_out;
    float* m_attn = out + (size_t)B * C * HW;
    float* amap   = m_attn + (size_t)B * HW;

    k_qsum_l     <<<dim3(B, 2), 512>>>(q);
    k_qproj      <<<dim3(16, 8), 128>>>(w_qs_w, w_qs_b);
    k_wq         <<<dim3(NH, 8), 512>>>(w_kc_w, w_kc_b, w_kd_w, w_kd_b);
    k_scores_part<<<dim3(B, 4, 8), 128>>>(v);
    k_vbar       <<<dim3(B, 16), 256>>>(v);
    k_attn       <<<dim3(NH, 8), 256>>>(w_vs_w, w_vs_b);
    k_out        <<<B * C / 4, 256>>>(v, bn_g, bn_b, bn_m, bn_v, out, amap);
    k_m          <<<B, 1024>>>(w_m_w, w_m_b, m_attn);
}

// round 16
// speedup vs baseline: 1.0502x; 1.0502x over previous
#include <cuda_runtime.h>
#include <math.h>

#define B   32
#define L   64
#define DQ  1024
#define C   512
#define NH  8
#define DK  64
#define HW  1024
#define TEMP_INV 0.125f   // 1/sqrt(64)

typedef unsigned long long ull;

__device__ __forceinline__ ull pack2(float lo, float hi) {
    ull r; asm("mov.b64 %0, {%1,%2};" : "=l"(r) : "f"(lo), "f"(hi)); return r;
}
__device__ __forceinline__ void ffma2(ull& d, ull a, ull b) {
    asm("fma.rn.f32x2 %0, %1, %2, %0;" : "+l"(d) : "l"(a), "l"(b));
}
__device__ __forceinline__ float2 unpack2(ull v) {
    float2 f; asm("mov.b64 {%0,%1}, %2;" : "=f"(f.x), "=f"(f.y) : "l"(v)); return f;
}
__device__ __forceinline__ void red_v4(float* dst, float a, float b, float c, float d) {
    asm volatile("red.global.add.v4.f32 [%0], {%1,%2,%3,%4};"
                 :: "l"(dst), "f"(a), "f"(b), "f"(c), "f"(d) : "memory");
}

// ---------------- scratch ----------------
__device__ __align__(16) float g_qs  [B*DQ];
__device__ __align__(16) float g_qsum[B*C];
__device__ __align__(16) float g_wqc [B*C*NH];      // [b][c][n]
__device__ __align__(16) float g_wqd [B*C*NH];      // [b][c][n]
__device__              float g_bqc [B*NH];
__device__              float g_bqd [B*NH];
__device__ __align__(16) float g_score[B*HW*16];    // [b][s][16]: 0-7 c-branch, 8-15 d-branch
__device__ __align__(16) float g_red [B*NH*8*2];    // per chunk (max, sumexp)
__device__ __align__(16) float g_dif [B*NH*HW];     // [b][n][s]
__device__ __align__(16) float g_vbar[B*NH*C];
__device__ __align__(16) float g_attn[B*C];

// ---- K1: qs[b,dq] = sum_l q[b,l,dq]. grid (B,4), block 256 ----
__global__ void __launch_bounds__(256) k_qsum_l(const float* __restrict__ q) {
    int b = blockIdx.x;
    int d = blockIdx.y * 256 + threadIdx.x;
    const float* p = q + (size_t)b * L * DQ + d;
    float s = 0.f;
#pragma unroll
    for (int l = 0; l < L; l++) s += p[(size_t)l * DQ];
    g_qs[b * DQ + d] = s;
}

// ---- K2: q_sum[b,o] = qs[b,:].w[o,:] + L*bias[o]. grid (16 oc, 8 bc of 4), block 128 ----
__global__ void __launch_bounds__(128) k_qproj(const float* __restrict__ w,
                                               const float* __restrict__ bias) {
    __shared__ __align__(16) float sq[4 * (DQ + 4)];
    int oc = blockIdx.x, bstart = blockIdx.y * 4;
    int tid = threadIdx.x;
    for (int i = tid; i < 4 * DQ / 4; i += 128) {
        int bb = i >> 8, c4 = i & 255;
        *(float4*)(sq + bb * (DQ + 4) + c4 * 4) =
            ((const float4*)g_qs)[(size_t)(bstart + bb) * 256 + c4];
    }
    __syncthreads();
    int o_local = tid >> 2, bb = tid & 3;
    int o = oc * 32 + o_local;
    const float4* wr = (const float4*)(w + (size_t)o * DQ);
    const float4* qr = (const float4*)(sq + bb * (DQ + 4));
    float acc = (float)L * bias[o];
#pragma unroll 8
    for (int k = 0; k < DQ / 4; k++) {
        float4 a = wr[k], x = qr[k];
        acc += a.x * x.x + a.y * x.y + a.z * x.z + a.w * x.w;
    }
    g_qsum[(bstart + bb) * C + o] = acc;
}

// ---- K3: wq[b][c][n] + bias dots. grid (NH, 8 bc of 4), block 512 ----
__global__ void __launch_bounds__(512) k_wq(const float* __restrict__ wkc, const float* __restrict__ bkc,
                                            const float* __restrict__ wkd, const float* __restrict__ bkd) {
    __shared__ float sq[4][DK];
    int n = blockIdx.x, bstart = blockIdx.y * 4;
    int c = threadIdx.x;
    if (c < 4 * DK) {
        int bb = c >> 6, d = c & 63;
        sq[bb][d] = g_qsum[(bstart + bb) * C + n * DK + d];
    }
    __syncthreads();
    float ac[4], ad[4];
#pragma unroll
    for (int bb = 0; bb < 4; bb++) { ac[bb] = 0.f; ad[bb] = 0.f; }
#pragma unroll 4
    for (int d = 0; d < DK; d++) {
        float wc = wkc[(size_t)(n * DK + d) * C + c];
        float wd = wkd[(size_t)(n * DK + d) * C + c];
#pragma unroll
        for (int bb = 0; bb < 4; bb++) {
            ac[bb] += wc * sq[bb][d];
            ad[bb] += wd * sq[bb][d];
        }
    }
#pragma unroll
    for (int bb = 0; bb < 4; bb++) {
        size_t idx = ((size_t)(bstart + bb) * C + c) * NH + n;
        g_wqc[idx] = ac[bb];
        g_wqd[idx] = ad[bb];
    }
    if (c < 4) {
        float s1 = 0.f, s2 = 0.f;
        for (int d = 0; d < DK; d++) {
            s1 += bkc[n * DK + d] * sq[c][d];
            s2 += bkd[n * DK + d] * sq[c][d];
        }
        int bn = (bstart + c) * NH + n;
        g_bqc[bn] = s1; g_bqd[bn] = s2;
    }
}

// ---- K4a: score partials. grid (B, 4 sh of 256 s, 8 cc of 64 c), block 128, 2 s/thread ----
__global__ void __launch_bounds__(128) k_scores_part(const float* __restrict__ v) {
    __shared__ __align__(16) float sw[64 * 16];   // [c][16]: 0-7 wqc, 8-15 wqd. 4KB
    int b = blockIdx.x, sh = blockIdx.y, cc = blockIdx.z;
    int tid = threadIdx.x;
    int cbase = cc * 64;
    for (int i = tid; i < 256; i += 128) {
        int ci = i >> 2, part = i & 3;
        const float* src = ((part < 2) ? g_wqc : g_wqd)
                         + ((size_t)(b * C + cbase + ci)) * NH + (part & 1) * 4;
        *(float4*)(sw + ci * 16 + ((part < 2) ? 0 : 8) + (part & 1) * 4) = *(const float4*)src;
    }
    __syncthreads();
    int s0 = sh * 256 + tid * 2;
    const float* vbase = v + ((size_t)(b * C + cbase)) * HW + s0;
    ull acc[2][8];
#pragma unroll
    for (int si = 0; si < 2; si++)
#pragma unroll
        for (int kp = 0; kp < 8; kp++) acc[si][kp] = 0ull;
    float2 cur[4], nxt[4];
#pragma unroll
    for (int u = 0; u < 4; u++) cur[u] = *(const float2*)(vbase + (size_t)u * HW);
#pragma unroll 2
    for (int cb = 0; cb < 64; cb += 4) {
        if (cb + 4 < 64) {
#pragma unroll
            for (int u = 0; u < 4; u++)
                nxt[u] = *(const float2*)(vbase + (size_t)(cb + 4 + u) * HW);
        }
#pragma unroll
        for (int u = 0; u < 4; u++) {
            const ulonglong2* w2 = (const ulonglong2*)(sw + (cb + u) * 16);
            ulonglong2 wa = w2[0], wb = w2[1], wc = w2[2], wd = w2[3];
            float2 cv = cur[u];
            ull v0 = pack2(cv.x, cv.x);
            ull v1 = pack2(cv.y, cv.y);
            ffma2(acc[0][0], v0, wa.x); ffma2(acc[0][1], v0, wa.y);
            ffma2(acc[0][2], v0, wb.x); ffma2(acc[0][3], v0, wb.y);
            ffma2(acc[0][4], v0, wc.x); ffma2(acc[0][5], v0, wc.y);
            ffma2(acc[0][6], v0, wd.x); ffma2(acc[0][7], v0, wd.y);
            ffma2(acc[1][0], v1, wa.x); ffma2(acc[1][1], v1, wa.y);
            ffma2(acc[1][2], v1, wb.x); ffma2(acc[1][3], v1, wb.y);
            ffma2(acc[1][4], v1, wc.x); ffma2(acc[1][5], v1, wc.y);
            ffma2(acc[1][6], v1, wd.x); ffma2(acc[1][7], v1, wd.y);
        }
#pragma unroll
        for (int u = 0; u < 4; u++) cur[u] = nxt[u];
    }
#pragma unroll
    for (int si = 0; si < 2; si++) {
        float* dst = g_score + ((size_t)b * HW + s0 + si) * 16;
        float2 f0 = unpack2(acc[si][0]), f1 = unpack2(acc[si][1]);
        float2 f2 = unpack2(acc[si][2]), f3 = unpack2(acc[si][3]);
        float2 f4 = unpack2(acc[si][4]), f5 = unpack2(acc[si][5]);
        float2 f6 = unpack2(acc[si][6]), f7 = unpack2(acc[si][7]);
        red_v4(dst,      f0.x, f0.y, f1.x, f1.y);
        red_v4(dst + 4,  f2.x, f2.y, f3.x, f3.y);
        red_v4(dst + 8,  f4.x, f4.y, f5.x, f5.y);
        red_v4(dst + 12, f6.x, f6.y, f7.x, f7.y);
    }
}

// ---- K4b: finalize: bias+scale, per-chunk softmax stats, sigmoid dif. grid (B,8), block 128 ----
__global__ void __launch_bounds__(128) k_sfin() {
    __shared__ float redm[4][8], redz[4][8];
    int b = blockIdx.x, sc = blockIdx.y;
    int tid = threadIdx.x;
    int s = sc * 128 + tid;
    int bn0 = b * NH;
    float4* gs = (float4*)(g_score + ((size_t)b * HW + s) * 16);
    float4 r0 = gs[0], r1 = gs[1], r2 = gs[2], r3 = gs[3];
    float x[8];
    x[0] = (r0.x + g_bqc[bn0 + 0]) * TEMP_INV;
    x[1] = (r0.y + g_bqc[bn0 + 1]) * TEMP_INV;
    x[2] = (r0.z + g_bqc[bn0 + 2]) * TEMP_INV;
    x[3] = (r0.w + g_bqc[bn0 + 3]) * TEMP_INV;
    x[4] = (r1.x + g_bqc[bn0 + 4]) * TEMP_INV;
    x[5] = (r1.y + g_bqc[bn0 + 5]) * TEMP_INV;
    x[6] = (r1.z + g_bqc[bn0 + 6]) * TEMP_INV;
    x[7] = (r1.w + g_bqc[bn0 + 7]) * TEMP_INV;
    gs[0] = make_float4(x[0], x[1], x[2], x[3]);
    gs[1] = make_float4(x[4], x[5], x[6], x[7]);
    int lane = tid & 31, w = tid >> 5;
#pragma unroll
    for (int n = 0; n < NH; n++) {
        float mm = x[n];
#pragma unroll
        for (int o = 16; o; o >>= 1) mm = fmaxf(mm, __shfl_xor_sync(0xffffffffu, mm, o));
        float z = expf(x[n] - mm);
#pragma unroll
        for (int o = 16; o; o >>= 1) z += __shfl_xor_sync(0xffffffffu, z, o);
        if (lane == 0) { redm[w][n] = mm; redz[w][n] = z; }
    }
    // d branch
    float y[8];
    y[0] = (r2.x + g_bqd[bn0 + 0]) * TEMP_INV;
    y[1] = (r2.y + g_bqd[bn0 + 1]) * TEMP_INV;
    y[2] = (r2.z + g_bqd[bn0 + 2]) * TEMP_INV;
    y[3] = (r2.w + g_bqd[bn0 + 3]) * TEMP_INV;
    y[4] = (r3.x + g_bqd[bn0 + 4]) * TEMP_INV;
    y[5] = (r3.y + g_bqd[bn0 + 5]) * TEMP_INV;
    y[6] = (r3.z + g_bqd[bn0 + 6]) * TEMP_INV;
    y[7] = (r3.w + g_bqd[bn0 + 7]) * TEMP_INV;
#pragma unroll
    for (int n = 0; n < NH; n++)
        g_dif[(size_t)(bn0 + n) * HW + s] = 1.f / (1.f + expf(-y[n]));
    __syncthreads();
    if (tid < 8) {
        int n = tid;
        float M = redm[0][n];
#pragma unroll
        for (int ww = 1; ww < 4; ww++) M = fmaxf(M, redm[ww][n]);
        float Z = 0.f;
#pragma unroll
        for (int ww = 0; ww < 4; ww++) Z += redz[ww][n] * expf(redm[ww][n] - M);
        *(float2*)(g_red + ((size_t)(bn0 + n) * 8 + sc) * 2) = make_float2(M, Z);
    }
}

// ---- K5: vbar[b,n,c] = sum_s softmax(score)[s,n] * v[b,c,s]. grid (B,16 cc of 32), block 256 ----
__global__ void __launch_bounds__(256) k_vbar(const float* __restrict__ v) {
    __shared__ __align__(16) ull sp[4352];          // swizzled: phys = i + (i>>4), i = s*4+np
    __shared__ float sM[8], sI[8];
    int b = blockIdx.x, t = threadIdx.x;
    if (t < 8) {
        int n = t;
        float M = -1e30f;
        float2 rz[8];
#pragma unroll
        for (int ch = 0; ch < 8; ch++) {
            rz[ch] = *(const float2*)(g_red + ((size_t)(b * NH + n) * 8 + ch) * 2);
            M = fmaxf(M, rz[ch].x);
        }
        float Z = 0.f;
#pragma unroll
        for (int ch = 0; ch < 8; ch++) Z += rz[ch].y * expf(rz[ch].x - M);
        sM[n] = M; sI[n] = 1.f / Z;
    }
    __syncthreads();
    for (int i = t; i < 4096; i += 256) {
        int s = i >> 2, np = i & 3;
        float2 xx = *(const float2*)(g_score + ((size_t)b * HW + s) * 16 + 2 * np);
        float e0 = expf(xx.x - sM[2 * np]) * sI[2 * np];
        float e1 = expf(xx.y - sM[2 * np + 1]) * sI[2 * np + 1];
        sp[i + (i >> 4)] = pack2(e0, e1);
    }
    __syncthreads();
    int warp = t >> 5, lane = t & 31;
    int c0 = blockIdx.y * 32 + warp * 4;
    const float* vb = v + (size_t)(b * C + c0) * HW;
    ull acc[4][4];
#pragma unroll
    for (int ci = 0; ci < 4; ci++)
#pragma unroll
        for (int np = 0; np < 4; np++) acc[ci][np] = 0ull;
    float4 vv[4], vn[4];
#pragma unroll
    for (int ci = 0; ci < 4; ci++)
        vv[ci] = *(const float4*)(vb + (size_t)ci * HW + lane * 4);
#pragma unroll 1
    for (int it = 0; it < 8; it++) {
        if (it < 7) {
#pragma unroll
            for (int ci = 0; ci < 4; ci++)
                vn[ci] = *(const float4*)(vb + (size_t)ci * HW + (it + 1) * 128 + lane * 4);
        }
        int sb = it * 32 + lane;
#pragma unroll
        for (int si = 0; si < 4; si++) {
            int s = it * 128 + lane * 4 + si;
            int phys = 4 * s + sb;
            ull pA0 = sp[phys];
            ull pA1 = sp[phys + 1];
            ull pB0 = sp[phys + 2];
            ull pB1 = sp[phys + 3];
#pragma unroll
            for (int ci = 0; ci < 4; ci++) {
                float vs = ((const float*)&vv[ci])[si];
                ull vd = pack2(vs, vs);
                ffma2(acc[ci][0], vd, pA0);
                ffma2(acc[ci][1], vd, pA1);
                ffma2(acc[ci][2], vd, pB0);
                ffma2(acc[ci][3], vd, pB1);
            }
        }
#pragma unroll
        for (int ci = 0; ci < 4; ci++) vv[ci] = vn[ci];
    }
#pragma unroll
    for (int ci = 0; ci < 4; ci++) {
#pragma unroll
        for (int np = 0; np < 4; np++) {
            float2 f = unpack2(acc[ci][np]);
#pragma unroll
            for (int o = 16; o; o >>= 1) {
                f.x += __shfl_xor_sync(0xffffffffu, f.x, o);
                f.y += __shfl_xor_sync(0xffffffffu, f.y, o);
            }
            if (lane == 0) {
                g_vbar[(size_t)(b * NH + 2 * np) * C + c0 + ci]     = f.x;
                g_vbar[(size_t)(b * NH + 2 * np + 1) * C + c0 + ci] = f.y;
            }
        }
    }
}

// ---- K6: attn[b,o] = w_vs[o,:].vbar[b,head(o),:]+bias. grid (NH, 8 bc of 4), block 256 ----
__global__ void __launch_bounds__(256) k_attn(const float* __restrict__ wvs,
                                              const float* __restrict__ bvs) {
    __shared__ __align__(16) float svb[4 * (C + 4)];
    int n = blockIdx.x, bstart = blockIdx.y * 4;
    int tid = threadIdx.x;
    for (int i = tid; i < 4 * C / 4; i += 256) {
        int bb = i >> 7, c4 = i & 127;
        *(float4*)(svb + bb * (C + 4) + c4 * 4) =
            ((const float4*)g_vbar)[(size_t)((bstart + bb) * NH + n) * 128 + c4];
    }
    __syncthreads();
    int o_local = tid >> 2, bb = tid & 3;
    int o = n * DK + o_local;
    const float4* wr = (const float4*)(wvs + (size_t)o * C);
    const float4* xr = (const float4*)(svb + bb * (C + 4));
    float acc = bvs[o];
#pragma unroll 8
    for (int k = 0; k < C / 4; k++) {
        float4 a = wr[k], x = xr[k];
        acc += a.x * x.x + a.y * x.y + a.z * x.z + a.w * x.w;
    }
    g_attn[(bstart + bb) * C + o] = acc;
}

// ---- K7: out + attn_map (streamer), 8 c per CTA. grid B*C/8 ----
__global__ void __launch_bounds__(256) k_out(const float* __restrict__ v, const float* __restrict__ gam,
                      const float* __restrict__ bet, const float* __restrict__ mean,
                      const float* __restrict__ var, float* __restrict__ out,
                      float* __restrict__ amap) {
    __shared__ float sd[HW + HW / 32];
    int blk = blockIdx.x;                 // b*64 + cchunk
    int b = blk >> 6, cbase = (blk & 63) * 8, n = cbase >> 6;
    int t4 = threadIdx.x * 4;
    const float* gdif = g_dif + (size_t)(b * NH + n) * HW;
#pragma unroll
    for (int u = 0; u < 4; u++) { int s = t4 + u; sd[s + (s >> 5)] = gdif[s]; }
    __syncthreads();
    int i0 = t4 >> 5, j0 = t4 & 31;
    float dd[4];
#pragma unroll
    for (int u = 0; u < 4; u++) dd[u] = sd[(j0 + u) * 33 + i0];
#pragma unroll
    for (int u = 0; u < 8; u++) {
        int c = cbase + u;
        float a  = g_attn[b * C + c];
        float sc = gam[c] * rsqrtf(var[c] + 1e-5f);
        float mn = mean[c], bt = bet[c];
        size_t base = ((size_t)(b * C + c)) * HW + t4;
        float4 rv = *(const float4*)(v + base);
        const float* rvp = (const float*)&rv;
        float vals[4], os[4];
#pragma unroll
        for (int k = 0; k < 4; k++) {
            float val = dd[k] * a;
            vals[k] = val;
            float o2 = (val - mn) * sc + bt + rvp[k];
            os[k] = o2 >= 0.f ? o2 : 0.1f * o2;
        }
        *(float4*)(amap + base) = *(float4*)vals;
        *(float4*)(out  + base) = *(float4*)os;
    }
}

// ---- K8: m_attn; sA parallelized over 576 threads ----
__global__ void k_m(const float* __restrict__ wm, const float* __restrict__ wmb,
                    float* __restrict__ m) {
    __shared__ float sd[NH][HW + 32];
    __shared__ float sA[NH * 9];
    int b = blockIdx.x, t = threadIdx.x;
    for (int n = 0; n < NH; n++) { int s = t; sd[n][s + (s >> 5)] = g_dif[(size_t)(b * NH + n) * HW + s]; }
    if (t < 576) {
        int g = t >> 3, sub = t & 7;       // g in [0,72)
        int nn = g / 9, k = g - nn * 9;
        float a = 0.f;
#pragma unroll
        for (int dd = 0; dd < 8; dd++) {
            int d = sub + dd * 8;
            a += g_attn[b * C + nn * DK + d] * wm[(size_t)(nn * DK + d) * 9 + k];
        }
        a += __shfl_xor_sync(0xffffffffu, a, 4);
        a += __shfl_xor_sync(0xffffffffu, a, 2);
        a += __shfl_xor_sync(0xffffffffu, a, 1);
        if (sub == 0) sA[g] = a;
    }
    __syncthreads();
    int i = t >> 5, j = t & 31;
    float acc = wmb[0];
#pragma unroll
    for (int n = 0; n < NH; n++) {
#pragma unroll
        for (int ki = 0; ki < 3; ki++) {
            int ii = i + ki - 1;
            if (ii < 0 || ii >= 32) continue;
#pragma unroll
            for (int kj = 0; kj < 3; kj++) {
                int jj = j + kj - 1;
                if (jj < 0 || jj >= 32) continue;
                acc += sA[n * 9 + ki * 3 + kj] * sd[n][jj * 33 + ii];
            }
        }
    }
    m[b * HW + i * 32 + j] = acc;
}

extern "C" void kernel_launch(void* const* d_in, const int* in_sizes, int n_in,
                              void* d_out, int out_size) {
    (void)in_sizes; (void)n_in; (void)out_size;
    const float* q      = (const float*)d_in[0];
    const float* v      = (const float*)d_in[1];
    const float* w_qs_w = (const float*)d_in[3];
    const float* w_qs_b = (const float*)d_in[4];
    const float* w_kc_w = (const float*)d_in[7];
    const float* w_kc_b = (const float*)d_in[8];
    const float* w_kd_w = (const float*)d_in[9];
    const float* w_kd_b = (const float*)d_in[10];
    const float* w_vs_w = (const float*)d_in[11];
    const float* w_vs_b = (const float*)d_in[12];
    const float* w_m_w  = (const float*)d_in[13];
    const float* w_m_b  = (const float*)d_in[14];
    const float* bn_g   = (const float*)d_in[15];
    const float* bn_b   = (const float*)d_in[16];
    const float* bn_m   = (const float*)d_in[17];
    const float* bn_v   = (const float*)d_in[18];

    float* out    = (float*)d_out;
    float* m_attn = out + (size_t)B * C * HW;
    float* amap   = m_attn + (size_t)B * HW;

    void* sc_ptr = nullptr;
    cudaGetSymbolAddress(&sc_ptr, g_score);
    cudaMemsetAsync(sc_ptr, 0, (size_t)B * HW * 16 * sizeof(float), 0);

    k_qsum_l     <<<dim3(B, 4), 256>>>(q);
    k_qproj      <<<dim3(16, 8), 128>>>(w_qs_w, w_qs_b);
    k_wq         <<<dim3(NH, 8), 512>>>(w_kc_w, w_kc_b, w_kd_w, w_kd_b);
    k_scores_part<<<dim3(B, 4, 8), 128>>>(v);
    k_sfin       <<<dim3(B, 8), 128>>>();
    k_vbar       <<<dim3(B, 16), 256>>>(v);
    k_attn       <<<dim3(NH, 8), 256>>>(w_vs_w, w_vs_b);
    k_out        <<<B * C / 8, 256>>>(v, bn_g, bn_b, bn_m, bn_v, out, amap);
    k_m          <<<B, 1024>>>(w_m_w, w_m_b, m_attn);
}

// round 17
// speedup vs baseline: 1.0673x; 1.0162x over previous
#include <cuda_runtime.h>
#include <math.h>

#define B   32
#define L   64
#define DQ  1024
#define C   512
#define NH  8
#define DK  64
#define HW  1024
#define TEMP_INV 0.125f   // 1/sqrt(64)

typedef unsigned long long ull;

__device__ __forceinline__ ull pack2(float lo, float hi) {
    ull r; asm("mov.b64 %0, {%1,%2};" : "=l"(r) : "f"(lo), "f"(hi)); return r;
}
__device__ __forceinline__ void ffma2(ull& d, ull a, ull b) {
    asm("fma.rn.f32x2 %0, %1, %2, %0;" : "+l"(d) : "l"(a), "l"(b));
}
__device__ __forceinline__ float2 unpack2(ull v) {
    float2 f; asm("mov.b64 {%0,%1}, %2;" : "=f"(f.x), "=f"(f.y) : "l"(v)); return f;
}
__device__ __forceinline__ void red_v4(float* dst, float a, float b, float c, float d) {
    asm volatile("red.global.add.v4.f32 [%0], {%1,%2,%3,%4};"
                 :: "l"(dst), "f"(a), "f"(b), "f"(c), "f"(d) : "memory");
}

// ---------------- scratch (zero-initialized at module load) ----------------
__device__ __align__(16) float g_qs  [B*DQ];
__device__ __align__(16) float g_qsum[B*C];
__device__ __align__(16) float g_wqc [B*C*NH];      // [b][c][n]
__device__ __align__(16) float g_wqd [B*C*NH];      // [b][c][n]
__device__              float g_bqc [B*NH];
__device__              float g_bqd [B*NH];
__device__ __align__(16) float g_score[B*HW*16];    // [b][s][16] — always left zeroed by sfin
__device__ __align__(16) float g_xs  [B*HW*8];      // [b][s][8] biased c-scores
__device__ __align__(16) float g_red [B*NH*8*2];    // per chunk (max, sumexp)
__device__ __align__(16) float g_dif [B*NH*HW];     // [b][n][s]
__device__ __align__(16) float g_vbar[B*NH*C];
__device__ __align__(16) float g_attn[B*C];

// ---- K1: qs[b,dq] = sum_l q[b,l,dq]. grid (B,4), block 256 ----
__global__ void __launch_bounds__(256) k_qsum_l(const float* __restrict__ q) {
    int b = blockIdx.x;
    int d = blockIdx.y * 256 + threadIdx.x;
    const float* p = q + (size_t)b * L * DQ + d;
    float s = 0.f;
#pragma unroll
    for (int l = 0; l < L; l++) s += p[(size_t)l * DQ];
    g_qs[b * DQ + d] = s;
}

// ---- K2: q_sum[b,o] = qs[b,:].w[o,:] + L*bias[o]. grid (16 oc, 8 bc of 4), block 128 ----
__global__ void __launch_bounds__(128) k_qproj(const float* __restrict__ w,
                                               const float* __restrict__ bias) {
    __shared__ __align__(16) float sq[4 * (DQ + 4)];
    int oc = blockIdx.x, bstart = blockIdx.y * 4;
    int tid = threadIdx.x;
    for (int i = tid; i < 4 * DQ / 4; i += 128) {
        int bb = i >> 8, c4 = i & 255;
        *(float4*)(sq + bb * (DQ + 4) + c4 * 4) =
            ((const float4*)g_qs)[(size_t)(bstart + bb) * 256 + c4];
    }
    __syncthreads();
    int o_local = tid >> 2, bb = tid & 3;
    int o = oc * 32 + o_local;
    const float4* wr = (const float4*)(w + (size_t)o * DQ);
    const float4* qr = (const float4*)(sq + bb * (DQ + 4));
    float acc = (float)L * bias[o];
#pragma unroll 8
    for (int k = 0; k < DQ / 4; k++) {
        float4 a = wr[k], x = qr[k];
        acc += a.x * x.x + a.y * x.y + a.z * x.z + a.w * x.w;
    }
    g_qsum[(bstart + bb) * C + o] = acc;
}

// ---- K3: wq[b][c][n] + bias dots. grid (NH, 8 bc of 4), block 512 ----
__global__ void __launch_bounds__(512) k_wq(const float* __restrict__ wkc, const float* __restrict__ bkc,
                                            const float* __restrict__ wkd, const float* __restrict__ bkd) {
    __shared__ float sq[4][DK];
    int n = blockIdx.x, bstart = blockIdx.y * 4;
    int c = threadIdx.x;
    if (c < 4 * DK) {
        int bb = c >> 6, d = c & 63;
        sq[bb][d] = g_qsum[(bstart + bb) * C + n * DK + d];
    }
    __syncthreads();
    float ac[4], ad[4];
#pragma unroll
    for (int bb = 0; bb < 4; bb++) { ac[bb] = 0.f; ad[bb] = 0.f; }
#pragma unroll 4
    for (int d = 0; d < DK; d++) {
        float wc = wkc[(size_t)(n * DK + d) * C + c];
        float wd = wkd[(size_t)(n * DK + d) * C + c];
#pragma unroll
        for (int bb = 0; bb < 4; bb++) {
            ac[bb] += wc * sq[bb][d];
            ad[bb] += wd * sq[bb][d];
        }
    }
#pragma unroll
    for (int bb = 0; bb < 4; bb++) {
        size_t idx = ((size_t)(bstart + bb) * C + c) * NH + n;
        g_wqc[idx] = ac[bb];
        g_wqd[idx] = ad[bb];
    }
    if (c < 4) {
        float s1 = 0.f, s2 = 0.f;
        for (int d = 0; d < DK; d++) {
            s1 += bkc[n * DK + d] * sq[c][d];
            s2 += bkd[n * DK + d] * sq[c][d];
        }
        int bn = (bstart + c) * NH + n;
        g_bqc[bn] = s1; g_bqd[bn] = s2;
    }
}

// ---- K4a: score partials. grid (B, 4 sh of 256 s, 8 cc of 64 c), block 128, 2 s/thread ----
__global__ void __launch_bounds__(128) k_scores_part(const float* __restrict__ v) {
    __shared__ __align__(16) float sw[64 * 16];   // [c][16]: 0-7 wqc, 8-15 wqd. 4KB
    int b = blockIdx.x, sh = blockIdx.y, cc = blockIdx.z;
    int tid = threadIdx.x;
    int cbase = cc * 64;
    for (int i = tid; i < 256; i += 128) {
        int ci = i >> 2, part = i & 3;
        const float* src = ((part < 2) ? g_wqc : g_wqd)
                         + ((size_t)(b * C + cbase + ci)) * NH + (part & 1) * 4;
        *(float4*)(sw + ci * 16 + ((part < 2) ? 0 : 8) + (part & 1) * 4) = *(const float4*)src;
    }
    __syncthreads();
    int s0 = sh * 256 + tid * 2;
    const float* vbase = v + ((size_t)(b * C + cbase)) * HW + s0;
    ull acc[2][8];
#pragma unroll
    for (int si = 0; si < 2; si++)
#pragma unroll
        for (int kp = 0; kp < 8; kp++) acc[si][kp] = 0ull;
    float2 cur[4], nxt[4];
#pragma unroll
    for (int u = 0; u < 4; u++) cur[u] = *(const float2*)(vbase + (size_t)u * HW);
#pragma unroll 2
    for (int cb = 0; cb < 64; cb += 4) {
        if (cb + 4 < 64) {
#pragma unroll
            for (int u = 0; u < 4; u++)
                nxt[u] = *(const float2*)(vbase + (size_t)(cb + 4 + u) * HW);
        }
#pragma unroll
        for (int u = 0; u < 4; u++) {
            const ulonglong2* w2 = (const ulonglong2*)(sw + (cb + u) * 16);
            ulonglong2 wa = w2[0], wb = w2[1], wc = w2[2], wd = w2[3];
            float2 cv = cur[u];
            ull v0 = pack2(cv.x, cv.x);
            ull v1 = pack2(cv.y, cv.y);
            ffma2(acc[0][0], v0, wa.x); ffma2(acc[0][1], v0, wa.y);
            ffma2(acc[0][2], v0, wb.x); ffma2(acc[0][3], v0, wb.y);
            ffma2(acc[0][4], v0, wc.x); ffma2(acc[0][5], v0, wc.y);
            ffma2(acc[0][6], v0, wd.x); ffma2(acc[0][7], v0, wd.y);
            ffma2(acc[1][0], v1, wa.x); ffma2(acc[1][1], v1, wa.y);
            ffma2(acc[1][2], v1, wb.x); ffma2(acc[1][3], v1, wb.y);
            ffma2(acc[1][4], v1, wc.x); ffma2(acc[1][5], v1, wc.y);
            ffma2(acc[1][6], v1, wd.x); ffma2(acc[1][7], v1, wd.y);
        }
#pragma unroll
        for (int u = 0; u < 4; u++) cur[u] = nxt[u];
    }
#pragma unroll
    for (int si = 0; si < 2; si++) {
        float* dst = g_score + ((size_t)b * HW + s0 + si) * 16;
        float2 f0 = unpack2(acc[si][0]), f1 = unpack2(acc[si][1]);
        float2 f2 = unpack2(acc[si][2]), f3 = unpack2(acc[si][3]);
        float2 f4 = unpack2(acc[si][4]), f5 = unpack2(acc[si][5]);
        float2 f6 = unpack2(acc[si][6]), f7 = unpack2(acc[si][7]);
        red_v4(dst,      f0.x, f0.y, f1.x, f1.y);
        red_v4(dst + 4,  f2.x, f2.y, f3.x, f3.y);
        red_v4(dst + 8,  f4.x, f4.y, f5.x, f5.y);
        red_v4(dst + 12, f6.x, f6.y, f7.x, f7.y);
    }
}

// ---- K4b: finalize: bias+scale -> g_xs, softmax stats -> g_red, sigmoid -> g_dif,
//      and re-zero g_score (replaces the memset). grid (B,8), block 128 ----
__global__ void __launch_bounds__(128) k_sfin() {
    __shared__ float redm[4][8], redz[4][8];
    int b = blockIdx.x, sc = blockIdx.y;
    int tid = threadIdx.x;
    int s = sc * 128 + tid;
    int bn0 = b * NH;
    float4* gs = (float4*)(g_score + ((size_t)b * HW + s) * 16);
    float4 r0 = gs[0], r1 = gs[1], r2 = gs[2], r3 = gs[3];
    float x[8];
    x[0] = (r0.x + g_bqc[bn0 + 0]) * TEMP_INV;
    x[1] = (r0.y + g_bqc[bn0 + 1]) * TEMP_INV;
    x[2] = (r0.z + g_bqc[bn0 + 2]) * TEMP_INV;
    x[3] = (r0.w + g_bqc[bn0 + 3]) * TEMP_INV;
    x[4] = (r1.x + g_bqc[bn0 + 4]) * TEMP_INV;
    x[5] = (r1.y + g_bqc[bn0 + 5]) * TEMP_INV;
    x[6] = (r1.z + g_bqc[bn0 + 6]) * TEMP_INV;
    x[7] = (r1.w + g_bqc[bn0 + 7]) * TEMP_INV;
    float4* xs = (float4*)(g_xs + ((size_t)b * HW + s) * 8);
    xs[0] = make_float4(x[0], x[1], x[2], x[3]);
    xs[1] = make_float4(x[4], x[5], x[6], x[7]);
    // re-zero the accumulator slab for the next graph replay
    float4 z4 = make_float4(0.f, 0.f, 0.f, 0.f);
    gs[0] = z4; gs[1] = z4; gs[2] = z4; gs[3] = z4;
    int lane = tid & 31, w = tid >> 5;
#pragma unroll
    for (int n = 0; n < NH; n++) {
        float mm = x[n];
#pragma unroll
        for (int o = 16; o; o >>= 1) mm = fmaxf(mm, __shfl_xor_sync(0xffffffffu, mm, o));
        float z = expf(x[n] - mm);
#pragma unroll
        for (int o = 16; o; o >>= 1) z += __shfl_xor_sync(0xffffffffu, z, o);
        if (lane == 0) { redm[w][n] = mm; redz[w][n] = z; }
    }
    // d branch
    float y[8];
    y[0] = (r2.x + g_bqd[bn0 + 0]) * TEMP_INV;
    y[1] = (r2.y + g_bqd[bn0 + 1]) * TEMP_INV;
    y[2] = (r2.z + g_bqd[bn0 + 2]) * TEMP_INV;
    y[3] = (r2.w + g_bqd[bn0 + 3]) * TEMP_INV;
    y[4] = (r3.x + g_bqd[bn0 + 4]) * TEMP_INV;
    y[5] = (r3.y + g_bqd[bn0 + 5]) * TEMP_INV;
    y[6] = (r3.z + g_bqd[bn0 + 6]) * TEMP_INV;
    y[7] = (r3.w + g_bqd[bn0 + 7]) * TEMP_INV;
#pragma unroll
    for (int n = 0; n < NH; n++)
        g_dif[(size_t)(bn0 + n) * HW + s] = 1.f / (1.f + expf(-y[n]));
    __syncthreads();
    if (tid < 8) {
        int n = tid;
        float M = redm[0][n];
#pragma unroll
        for (int ww = 1; ww < 4; ww++) M = fmaxf(M, redm[ww][n]);
        float Z = 0.f;
#pragma unroll
        for (int ww = 0; ww < 4; ww++) Z += redz[ww][n] * expf(redm[ww][n] - M);
        *(float2*)(g_red + ((size_t)(bn0 + n) * 8 + sc) * 2) = make_float2(M, Z);
    }
}

// ---- K5: vbar[b,n,c] = sum_s softmax(xs)[s,n] * v[b,c,s]. grid (B,16 cc of 32), block 256 ----
__global__ void __launch_bounds__(256) k_vbar(const float* __restrict__ v) {
    __shared__ __align__(16) ull sp[4352];          // swizzled: phys = i + (i>>4), i = s*4+np
    __shared__ float sM[8], sI[8];
    int b = blockIdx.x, t = threadIdx.x;
    if (t < 8) {
        int n = t;
        float M = -1e30f;
        float2 rz[8];
#pragma unroll
        for (int ch = 0; ch < 8; ch++) {
            rz[ch] = *(const float2*)(g_red + ((size_t)(b * NH + n) * 8 + ch) * 2);
            M = fmaxf(M, rz[ch].x);
        }
        float Z = 0.f;
#pragma unroll
        for (int ch = 0; ch < 8; ch++) Z += rz[ch].y * expf(rz[ch].x - M);
        sM[n] = M; sI[n] = 1.f / Z;
    }
    __syncthreads();
    for (int i = t; i < 4096; i += 256) {
        int s = i >> 2, np = i & 3;
        float2 xx = *(const float2*)(g_xs + ((size_t)b * HW + s) * 8 + 2 * np);
        float e0 = expf(xx.x - sM[2 * np]) * sI[2 * np];
        float e1 = expf(xx.y - sM[2 * np + 1]) * sI[2 * np + 1];
        sp[i + (i >> 4)] = pack2(e0, e1);
    }
    __syncthreads();
    int warp = t >> 5, lane = t & 31;
    int c0 = blockIdx.y * 32 + warp * 4;
    const float* vb = v + (size_t)(b * C + c0) * HW;
    ull acc[4][4];
#pragma unroll
    for (int ci = 0; ci < 4; ci++)
#pragma unroll
        for (int np = 0; np < 4; np++) acc[ci][np] = 0ull;
    float4 vv[4], vn[4];
#pragma unroll
    for (int ci = 0; ci < 4; ci++)
        vv[ci] = *(const float4*)(vb + (size_t)ci * HW + lane * 4);
#pragma unroll 1
    for (int it = 0; it < 8; it++) {
        if (it < 7) {
#pragma unroll
            for (int ci = 0; ci < 4; ci++)
                vn[ci] = *(const float4*)(vb + (size_t)ci * HW + (it + 1) * 128 + lane * 4);
        }
        int sb = it * 32 + lane;
#pragma unroll
        for (int si = 0; si < 4; si++) {
            int s = it * 128 + lane * 4 + si;
            int phys = 4 * s + sb;
            ull pA0 = sp[phys];
            ull pA1 = sp[phys + 1];
            ull pB0 = sp[phys + 2];
            ull pB1 = sp[phys + 3];
#pragma unroll
            for (int ci = 0; ci < 4; ci++) {
                float vs = ((const float*)&vv[ci])[si];
                ull vd = pack2(vs, vs);
                ffma2(acc[ci][0], vd, pA0);
                ffma2(acc[ci][1], vd, pA1);
                ffma2(acc[ci][2], vd, pB0);
                ffma2(acc[ci][3], vd, pB1);
            }
        }
#pragma unroll
        for (int ci = 0; ci < 4; ci++) vv[ci] = vn[ci];
    }
#pragma unroll
    for (int ci = 0; ci < 4; ci++) {
#pragma unroll
        for (int np = 0; np < 4; np++) {
            float2 f = unpack2(acc[ci][np]);
#pragma unroll
            for (int o = 16; o; o >>= 1) {
                f.x += __shfl_xor_sync(0xffffffffu, f.x, o);
                f.y += __shfl_xor_sync(0xffffffffu, f.y, o);
            }
            if (lane == 0) {
                g_vbar[(size_t)(b * NH + 2 * np) * C + c0 + ci]     = f.x;
                g_vbar[(size_t)(b * NH + 2 * np + 1) * C + c0 + ci] = f.y;
            }
        }
    }
}

// ---- K6: attn[b,o] = w_vs[o,:].vbar[b,head(o),:]+bias. grid (NH, 8 bc of 4), block 256 ----
__global__ void __launch_bounds__(256) k_attn(const float* __restrict__ wvs,
                                              const float* __restrict__ bvs) {
    __shared__ __align__(16) float svb[4 * (C + 4)];
    int n = blockIdx.x, bstart = blockIdx.y * 4;
    int tid = threadIdx.x;
    for (int i = tid; i < 4 * C / 4; i += 256) {
        int bb = i >> 7, c4 = i & 127;
        *(float4*)(svb + bb * (C + 4) + c4 * 4) =
            ((const float4*)g_vbar)[(size_t)((bstart + bb) * NH + n) * 128 + c4];
    }
    __syncthreads();
    int o_local = tid >> 2, bb = tid & 3;
    int o = n * DK + o_local;
    const float4* wr = (const float4*)(wvs + (size_t)o * C);
    const float4* xr = (const float4*)(svb + bb * (C + 4));
    float acc = bvs[o];
#pragma unroll 8
    for (int k = 0; k < C / 4; k++) {
        float4 a = wr[k], x = xr[k];
        acc += a.x * x.x + a.y * x.y + a.z * x.z + a.w * x.w;
    }
    g_attn[(bstart + bb) * C + o] = acc;
}

// ---- K7: out + attn_map (streamer), 8 c per CTA. grid B*C/8 ----
__global__ void __launch_bounds__(256) k_out(const float* __restrict__ v, const float* __restrict__ gam,
                      const float* __restrict__ bet, const float* __restrict__ mean,
                      const float* __restrict__ var, float* __restrict__ out,
                      float* __restrict__ amap) {
    __shared__ float sd[HW + HW / 32];
    int blk = blockIdx.x;                 // b*64 + cchunk
    int b = blk >> 6, cbase = (blk & 63) * 8, n = cbase >> 6;
    int t4 = threadIdx.x * 4;
    const float* gdif = g_dif + (size_t)(b * NH + n) * HW;
#pragma unroll
    for (int u = 0; u < 4; u++) { int s = t4 + u; sd[s + (s >> 5)] = gdif[s]; }
    __syncthreads();
    int i0 = t4 >> 5, j0 = t4 & 31;
    float dd[4];
#pragma unroll
    for (int u = 0; u < 4; u++) dd[u] = sd[(j0 + u) * 33 + i0];
#pragma unroll
    for (int u = 0; u < 8; u++) {
        int c = cbase + u;
        float a  = g_attn[b * C + c];
        float sc = gam[c] * rsqrtf(var[c] + 1e-5f);
        float mn = mean[c], bt = bet[c];
        size_t base = ((size_t)(b * C + c)) * HW + t4;
        float4 rv = *(const float4*)(v + base);
        const float* rvp = (const float*)&rv;
        float vals[4], os[4];
#pragma unroll
        for (int k = 0; k < 4; k++) {
            float val = dd[k] * a;
            vals[k] = val;
            float o2 = (val - mn) * sc + bt + rvp[k];
            os[k] = o2 >= 0.f ? o2 : 0.1f * o2;
        }
        *(float4*)(amap + base) = *(float4*)vals;
        *(float4*)(out  + base) = *(float4*)os;
    }
}

// ---- K8: m_attn; sA parallelized over 576 threads ----
__global__ void k_m(const float* __restrict__ wm, const float* __restrict__ wmb,
                    float* __restrict__ m) {
    __shared__ float sd[NH][HW + 32];
    __shared__ float sA[NH * 9];
    int b = blockIdx.x, t = threadIdx.x;
    for (int n = 0; n < NH; n++) { int s = t; sd[n][s + (s >> 5)] = g_dif[(size_t)(b * NH + n) * HW + s]; }
    if (t < 576) {
        int g = t >> 3, sub = t & 7;       // g in [0,72)
        int nn = g / 9, k = g - nn * 9;
        float a = 0.f;
#pragma unroll
        for (int dd = 0; dd < 8; dd++) {
            int d = sub + dd * 8;
            a += g_attn[b * C + nn * DK + d] * wm[(size_t)(nn * DK + d) * 9 + k];
        }
        a += __shfl_xor_sync(0xffffffffu, a, 4);
        a += __shfl_xor_sync(0xffffffffu, a, 2);
        a += __shfl_xor_sync(0xffffffffu, a, 1);
        if (sub == 0) sA[g] = a;
    }
    __syncthreads();
    int i = t >> 5, j = t & 31;
    float acc = wmb[0];
#pragma unroll
    for (int n = 0; n < NH; n++) {
#pragma unroll
        for (int ki = 0; ki < 3; ki++) {
            int ii = i + ki - 1;
            if (ii < 0 || ii >= 32) continue;
#pragma unroll
            for (int kj = 0; kj < 3; kj++) {
                int jj = j + kj - 1;
                if (jj < 0 || jj >= 32) continue;
                acc += sA[n * 9 + ki * 3 + kj] * sd[n][jj * 33 + ii];
            }
        }
    }
    m[b * HW + i * 32 + j] = acc;
}

extern "C" void kernel_launch(void* const* d_in, const int* in_sizes, int n_in,
                              void* d_out, int out_size) {
    (void)in_sizes; (void)n_in; (void)out_size;
    const float* q      = (const float*)d_in[0];
    const float* v      = (const float*)d_in[1];
    const float* w_qs_w = (const float*)d_in[3];
    const float* w_qs_b = (const float*)d_in[4];
    const float* w_kc_w = (const float*)d_in[7];
    const float* w_kc_b = (const float*)d_in[8];
    const float* w_kd_w = (const float*)d_in[9];
    const float* w_kd_b = (const float*)d_in[10];
    const float* w_vs_w = (const float*)d_in[11];
    const float* w_vs_b = (const float*)d_in[12];
    const float* w_m_w  = (const float*)d_in[13];
    const float* w_m_b  = (const float*)d_in[14];
    const float* bn_g   = (const float*)d_in[15];
    const float* bn_b   = (const float*)d_in[16];
    const float* bn_m   = (const float*)d_in[17];
    const float* bn_v   = (const float*)d_in[18];

    float* out    = (float*)d_out;
    float* m_attn = out + (size_t)B * C * HW;
    float* amap   = m_attn + (size_t)B * HW;

    k_qsum_l     <<<dim3(B, 4), 256>>>(q);
    k_qproj      <<<dim3(16, 8), 128>>>(w_qs_w, w_qs_b);
    k_wq         <<<dim3(NH, 8), 512>>>(w_kc_w, w_kc_b, w_kd_w, w_kd_b);
    k_scores_part<<<dim3(B, 4, 8), 128>>>(v);
    k_sfin       <<<dim3(B, 8), 128>>>();
    k_vbar       <<<dim3(B, 16), 256>>>(v);
    k_attn       <<<dim3(NH, 8), 256>>>(w_vs_w, w_vs_b);
    k_out        <<<B * C / 8, 256>>>(v, bn_g, bn_b, bn_m, bn_v, out, amap);
    k_m          <<<B, 1024>>>(w_m_w, w_m_b, m_attn);
}